// round 5
// baseline (speedup 1.0000x reference)
#include <cuda_runtime.h>
#include <cuda_bf16.h>
#include <cstdint>

#define N_NODES 50000
#define D_FEAT  128
#define N_EDGES 600000
#define CAP     96      // per-node bucket capacity (Poisson(12) max in-deg ~40)

// static scratch (no cudaMalloc allowed)
__device__ int g_cnt[N_NODES];
__device__ int g_bucket[N_NODES * CAP];
__device__ int g_is64;

// ---------------------------------------------------------------------------
// Kernel 1: zero counts; thread 0 also detects index dtype.
// int64 data (values < 2^31) read as int32 pairs => (val, 0, val, 0, ...).
// ---------------------------------------------------------------------------
__global__ void init_kernel(const int* __restrict__ idx_as_i32) {
    int i = blockIdx.x * blockDim.x + threadIdx.x;
    if (i < N_NODES) g_cnt[i] = 0;
    if (i == 0) {
        int is64 = 1;
        #pragma unroll 1
        for (int k = 0; k < 256; k++) {
            int lo = idx_as_i32[2 * k];
            int hi = idx_as_i32[2 * k + 1];
            if (hi != 0 || lo < 0 || lo >= N_NODES) { is64 = 0; break; }
        }
        g_is64 = is64;
    }
}

// ---------------------------------------------------------------------------
// Kernel 2: bin edges by destination. Two edges per thread, vector index loads.
// Edges past CAP are dropped here; agg_kernel recovers them by edge-list scan.
// ---------------------------------------------------------------------------
__device__ __forceinline__ void bin_edge(long long s, long long d) {
    if (s < 0 || s >= N_NODES || d < 0 || d >= N_NODES) return;
    int pos = atomicAdd(&g_cnt[(int)d], 1);
    if (pos < CAP) g_bucket[(int)d * CAP + pos] = (int)s;
}

__global__ void fill_kernel(const void* __restrict__ src_raw,
                            const void* __restrict__ dst_raw) {
    int t = blockIdx.x * blockDim.x + threadIdx.x;
    int e = t * 2;
    if (e >= N_EDGES) return;

    if (g_is64) {
        if (e + 1 < N_EDGES) {
            longlong2 s2 = __ldg((const longlong2*)src_raw + t);
            longlong2 d2 = __ldg((const longlong2*)dst_raw + t);
            bin_edge(s2.x, d2.x);
            bin_edge(s2.y, d2.y);
        } else {
            bin_edge(__ldg((const long long*)src_raw + e),
                     __ldg((const long long*)dst_raw + e));
        }
    } else {
        if (e + 1 < N_EDGES) {
            int2 s2 = __ldg((const int2*)src_raw + t);
            int2 d2 = __ldg((const int2*)dst_raw + t);
            bin_edge(s2.x, d2.x);
            bin_edge(s2.y, d2.y);
        } else {
            bin_edge((long long)__ldg((const int*)src_raw + e),
                     (long long)__ldg((const int*)dst_raw + e));
        }
    }
}

// ---------------------------------------------------------------------------
// Kernel 3: one warp per node. Gather-reduce bucketed sources, write mean once.
// Overflowed nodes (c > CAP, never in practice) rescan the edge list.
// ---------------------------------------------------------------------------
__global__ void agg_kernel(const float* __restrict__ emb,
                           float* __restrict__ out,
                           const void* __restrict__ src_raw,
                           const void* __restrict__ dst_raw) {
    int gtid = blockIdx.x * blockDim.x + threadIdx.x;
    int node = gtid >> 5;
    int lane = gtid & 31;
    if (node >= N_NODES) return;

    int c = g_cnt[node];
    int m = (c < CAP) ? c : CAP;
    const int* bk = g_bucket + node * CAP;

    float4 acc = make_float4(0.f, 0.f, 0.f, 0.f);

    for (int base = 0; base < m; base += 32) {
        int lim = m - base; if (lim > 32) lim = 32;
        int s_l = (lane < lim) ? bk[base + lane] : 0;
        #pragma unroll 4
        for (int e = 0; e < lim; e++) {
            int s = __shfl_sync(0xffffffffu, s_l, e);
            float4 v = __ldg((const float4*)(emb + (long long)s * D_FEAT) + lane);
            acc.x += v.x; acc.y += v.y; acc.z += v.z; acc.w += v.w;
        }
    }

    if (c > CAP) {
        // Rare overflow path: recover edges dropped by fill via full scan.
        // fill stores buckets in atomic order, so the CAP stored sources are
        // *some* CAP of this node's edges; we must add the others. Since
        // atomic ordering is nondeterministic, instead recompute exactly:
        // reset acc and sum ALL edges with dst==node from the edge list.
        acc = make_float4(0.f, 0.f, 0.f, 0.f);
        int is64 = g_is64;
        for (int e = 0; e < N_EDGES; e++) {
            long long d = is64 ? __ldg((const long long*)dst_raw + e)
                               : (long long)__ldg((const int*)dst_raw + e);
            if ((int)d != node) continue;
            long long s = is64 ? __ldg((const long long*)src_raw + e)
                               : (long long)__ldg((const int*)src_raw + e);
            if (s < 0 || s >= N_NODES) continue;
            float4 v = __ldg((const float4*)(emb + s * D_FEAT) + lane);
            acc.x += v.x; acc.y += v.y; acc.z += v.z; acc.w += v.w;
        }
    }

    float inv = (c > 0) ? (1.0f / (float)c) : 0.0f;
    acc.x *= inv; acc.y *= inv; acc.z *= inv; acc.w *= inv;
    ((float4*)out)[node * (D_FEAT / 4) + lane] = acc;
}

// ---------------------------------------------------------------------------
extern "C" void kernel_launch(void* const* d_in, const int* in_sizes, int n_in,
                              void* d_out, int out_size) {
    const float* emb = (const float*)d_in[0];
    const void*  src = d_in[1];
    const void*  dst = d_in[2];
    float* out = (float*)d_out;

    init_kernel<<<(N_NODES + 255) / 256, 256>>>((const int*)dst);
    fill_kernel<<<(N_EDGES / 2 + 255) / 256, 256>>>(src, dst);
    {
        long long total_threads = (long long)N_NODES * 32;
        agg_kernel<<<(int)((total_threads + 255) / 256), 256>>>(emb, out, src, dst);
    }
}